// round 11
// baseline (speedup 1.0000x reference)
#include <cuda_runtime.h>
#include <cuda_fp16.h>

// ---------------------------------------------------------------------------
// GNNEncoder: 2-layer GCN. out[d] = dinv[d]*sum_{(s,d)}(x[s]@W)*dinv[s] + b
// R11: 6-launch pipeline:
//   [hist, scan(self-cleaning cnt), fill, gemm1(TC split-mma),
//    FUSED agg1+relu+gemm2 (x2 lives only in smem fp16), agg2]
//   - k_init eliminated: inline dtype detect + self-cleaning histogram
//   - x2 global round-trip (51MB) eliminated via fusion
//   - hist/fill at 8 edges/thread (MLP 8)
// All scratch in __device__ globals; graph-capturable (kernel launches only).
// ---------------------------------------------------------------------------

#define NODES_MAX 50000
#define EDGES_MAX 800000

__device__ int    g_cnt[NODES_MAX];          // self-cleaning (zeroed by scan)
__device__ int    g_off[NODES_MAX + 1];
__device__ int    g_cursor[NODES_MAX];
__device__ int    g_csr_src[EDGES_MAX];
__device__ float  g_dinv[NODES_MAX];
__device__ __half g_hs [NODES_MAX * 128];    // layer1 (x@W1)*dinv  (gathered)
__device__ __half g_hs2[NODES_MAX * 64];     // layer2 (x2@W2)*dinv (gathered)

// ---- helpers ----------------------------------------------------------------
__device__ __forceinline__ unsigned sptr(const void* p)
{
    return (unsigned)__cvta_generic_to_shared(p);
}

__device__ __forceinline__ void ldm_x4(unsigned addr, unsigned& r0, unsigned& r1,
                                       unsigned& r2, unsigned& r3)
{
    asm volatile("ldmatrix.sync.aligned.m8n8.x4.shared.b16 {%0,%1,%2,%3}, [%4];"
                 : "=r"(r0), "=r"(r1), "=r"(r2), "=r"(r3) : "r"(addr));
}

__device__ __forceinline__ void ldm_x4t(unsigned addr, unsigned& r0, unsigned& r1,
                                        unsigned& r2, unsigned& r3)
{
    asm volatile("ldmatrix.sync.aligned.m8n8.x4.trans.shared.b16 {%0,%1,%2,%3}, [%4];"
                 : "=r"(r0), "=r"(r1), "=r"(r2), "=r"(r3) : "r"(addr));
}

__device__ __forceinline__ void mma16816(float* d, const unsigned* a,
                                         unsigned b0, unsigned b1)
{
    asm volatile(
        "mma.sync.aligned.m16n8k16.row.col.f32.f16.f16.f32 "
        "{%0,%1,%2,%3}, {%4,%5,%6,%7}, {%8,%9}, {%0,%1,%2,%3};"
        : "+f"(d[0]), "+f"(d[1]), "+f"(d[2]), "+f"(d[3])
        : "r"(a[0]), "r"(a[1]), "r"(a[2]), "r"(a[3]), "r"(b0), "r"(b1));
}

// split a float4 into hi/lo half2 pairs (x = h + l exactly to ~2^-22)
__device__ __forceinline__ void split4(float4 v, uint2& hi, uint2& lo)
{
    __half hx = __float2half_rn(v.x), hy = __float2half_rn(v.y);
    __half hz = __float2half_rn(v.z), hw = __float2half_rn(v.w);
    __half lx = __float2half_rn(v.x - __half2float(hx));
    __half ly = __float2half_rn(v.y - __half2float(hy));
    __half lz = __float2half_rn(v.z - __half2float(hz));
    __half lw = __float2half_rn(v.w - __half2float(hw));
    __half2 h01 = __halves2half2(hx, hy), h23 = __halves2half2(hz, hw);
    __half2 l01 = __halves2half2(lx, ly), l23 = __halves2half2(lz, lw);
    hi.x = *(unsigned*)&h01; hi.y = *(unsigned*)&h23;
    lo.x = *(unsigned*)&l01; lo.y = *(unsigned*)&l23;
}

// dtype detect: int64 viewed as int32 pairs -> odd words all zero.
// Reads one broadcast sector; values are fixed dataset node ids.
__device__ __forceinline__ bool is_int32(const int* __restrict__ v)
{
    return (v[1] | v[3] | v[5] | v[7]) != 0;
}

// ---- CSR build --------------------------------------------------------------
__global__ void k_hist(const int* __restrict__ v, int E, int N)
{
    int base = (blockIdx.x * blockDim.x + threadIdx.x) * 8;
    if (base >= E) return;
    bool is32 = is_int32(v);
    if (base + 8 <= E) {
        unsigned d[8];
        if (is32) {
            int4 a = *(const int4*)&v[E + base];
            int4 b = *(const int4*)&v[E + base + 4];
            d[0] = a.x; d[1] = a.y; d[2] = a.z; d[3] = a.w;
            d[4] = b.x; d[5] = b.y; d[6] = b.z; d[7] = b.w;
        } else {
            int4 a = *(const int4*)&v[2 * E + 2 * base];
            int4 b = *(const int4*)&v[2 * E + 2 * base + 4];
            int4 c = *(const int4*)&v[2 * E + 2 * base + 8];
            int4 e = *(const int4*)&v[2 * E + 2 * base + 12];
            d[0] = a.x; d[1] = a.z; d[2] = b.x; d[3] = b.z;
            d[4] = c.x; d[5] = c.z; d[6] = e.x; d[7] = e.z;
        }
#pragma unroll
        for (int j = 0; j < 8; j++)
            if (d[j] < (unsigned)N) atomicAdd(&g_cnt[d[j]], 1);
    } else {
        int s = is32 ? 1 : 2, dbase = is32 ? E : 2 * E;
        for (int i = base; i < E; i++) {
            unsigned d = (unsigned)v[dbase + s * i];
            if (d < (unsigned)N) atomicAdd(&g_cnt[d], 1);
        }
    }
}

// Single-block coalesced block-scan; zeroes g_cnt after reading (self-clean).
__global__ void __launch_bounds__(1024) k_scan1(int N, int E)
{
    __shared__ int wsum[32];
    __shared__ int stot;
    int t    = threadIdx.x;
    int lane = t & 31;
    int wid  = t >> 5;
    int carry = 0;
    int ntiles = (N + 1023) >> 10;

    for (int tile = 0; tile < ntiles; tile++) {
        int i = (tile << 10) + t;
        int c = 0;
        if (i < N) {
            c = g_cnt[i];
            g_cnt[i] = 0;                    // self-clean for next launch
        }
        int incl = c;
#pragma unroll
        for (int o = 1; o < 32; o <<= 1) {
            int vv = __shfl_up_sync(0xffffffffu, incl, o);
            if (lane >= o) incl += vv;
        }
        if (lane == 31) wsum[wid] = incl;
        __syncthreads();
        if (wid == 0) {
            int s  = wsum[lane];
            int si = s;
#pragma unroll
            for (int o = 1; o < 32; o <<= 1) {
                int vv = __shfl_up_sync(0xffffffffu, si, o);
                if (lane >= o) si += vv;
            }
            wsum[lane] = si - s;
            if (lane == 31) stot = si;
        }
        __syncthreads();
        int off = carry + wsum[wid] + incl - c;
        if (i < N) {
            g_off[i]    = off;
            g_cursor[i] = off;
            g_dinv[i]   = rsqrtf((float)(c + 1));   // +1 self loop
        }
        carry += stot;
        __syncthreads();
    }
    if (t == 0) g_off[N] = E;
}

__global__ void k_fill(const int* __restrict__ v, int E, int N)
{
    int base = (blockIdx.x * blockDim.x + threadIdx.x) * 8;
    if (base >= E) return;
    bool is32 = is_int32(v);
    if (base + 8 <= E) {
        unsigned s[8], d[8];
        if (is32) {
            int4 a = *(const int4*)&v[base];
            int4 b = *(const int4*)&v[base + 4];
            int4 c = *(const int4*)&v[E + base];
            int4 e = *(const int4*)&v[E + base + 4];
            s[0] = a.x; s[1] = a.y; s[2] = a.z; s[3] = a.w;
            s[4] = b.x; s[5] = b.y; s[6] = b.z; s[7] = b.w;
            d[0] = c.x; d[1] = c.y; d[2] = c.z; d[3] = c.w;
            d[4] = e.x; d[5] = e.y; d[6] = e.z; d[7] = e.w;
        } else {
#pragma unroll
            for (int u = 0; u < 4; u++) {
                int4 a = *(const int4*)&v[2 * base + 4 * u];
                int4 c = *(const int4*)&v[2 * E + 2 * base + 4 * u];
                s[2 * u] = a.x; s[2 * u + 1] = a.z;
                d[2 * u] = c.x; d[2 * u + 1] = c.z;
            }
        }
#pragma unroll
        for (int j = 0; j < 8; j++)
            if (d[j] < (unsigned)N && s[j] < (unsigned)N)
                g_csr_src[atomicAdd(&g_cursor[d[j]], 1)] = (int)s[j];
    } else {
        int st = is32 ? 1 : 2, dbase = is32 ? E : 2 * E;
        for (int i = base; i < E; i++) {
            unsigned d  = (unsigned)v[dbase + st * i];
            unsigned sr = (unsigned)v[st * i];
            if (d < (unsigned)N && sr < (unsigned)N)
                g_csr_src[atomicAdd(&g_cursor[d], 1)] = (int)sr;
        }
    }
}

// ---------------------------------------------------------------------------
// GEMM-1 (tensor core, 2-term split): g_hs[row] = fp16((X@W1)*dinv[row])
//   BM=64, 8 warps, warp tile 32x32, BK=32. Same as R10 (DOUT=128).
// ---------------------------------------------------------------------------
__global__ void __launch_bounds__(256)
k_gemm1(const float* __restrict__ X, const float* __restrict__ W, int N)
{
    constexpr int DOUT = 128;
    constexpr int BK   = 32;
    constexpr int BM   = 64;
    constexpr int SXH  = BK + 8;       // 40
    constexpr int SWH  = DOUT + 8;     // 136

    __shared__ __align__(16) __half xs_h[BM * SXH];
    __shared__ __align__(16) __half xs_l[BM * SXH];
    __shared__ __align__(16) __half ws_h[BK * SWH];
    __shared__ __align__(16) __half ws_l[BK * SWH];

    int t    = threadIdx.x;
    int w    = t >> 5;
    int lane = t & 31;
    int warpRow = w / 4;               // WC=4
    int warpCol = w % 4;
    int rowW0   = warpRow * 32;
    int colW0   = warpCol * 32;
    int row0    = blockIdx.x * BM;

    float acc[2][4][4];
#pragma unroll
    for (int mt = 0; mt < 2; mt++)
#pragma unroll
        for (int nt = 0; nt < 4; nt++)
#pragma unroll
            for (int q = 0; q < 4; q++) acc[mt][nt][q] = 0.f;

    int a_row = (lane & 15);
    int a_col = (lane >> 4) * 8;
    int b_row = ((lane >> 3) & 1) * 8 + (lane & 7);
    int b_col = (lane >> 4) * 8;

    for (int kk = 0; kk < 128; kk += BK) {
#pragma unroll
        for (int u = 0; u < BM / 32; u++) {
            int idx = u * 256 + t;
            int r   = idx >> 3;
            int j4  = idx & 7;
            int row = row0 + r;
            float4 x = make_float4(0.f, 0.f, 0.f, 0.f);
            if (row < N) x = *(const float4*)&X[row * 128 + kk + j4 * 4];
            uint2 hi, lo;
            split4(x, hi, lo);
            *(uint2*)&xs_h[r * SXH + j4 * 4] = hi;
            *(uint2*)&xs_l[r * SXH + j4 * 4] = lo;
        }
#pragma unroll
        for (int u = 0; u < DOUT / 32; u++) {
            int idx = u * 256 + t;
            int k   = idx / (DOUT / 4);
            int c4  = idx % (DOUT / 4);
            float4 wv = *(const float4*)&W[(kk + k) * DOUT + c4 * 4];
            uint2 hi, lo;
            split4(wv, hi, lo);
            *(uint2*)&ws_h[k * SWH + c4 * 4] = hi;
            *(uint2*)&ws_l[k * SWH + c4 * 4] = lo;
        }
        __syncthreads();

#pragma unroll
        for (int ks = 0; ks < BK; ks += 16) {
            unsigned ah[2][4], al[2][4];
#pragma unroll
            for (int mt = 0; mt < 2; mt++) {
                int r = rowW0 + mt * 16 + a_row;
                int c = ks + a_col;
                ldm_x4(sptr(&xs_h[r * SXH + c]), ah[mt][0], ah[mt][1], ah[mt][2], ah[mt][3]);
                ldm_x4(sptr(&xs_l[r * SXH + c]), al[mt][0], al[mt][1], al[mt][2], al[mt][3]);
            }
            unsigned bh[2][4], bl[2][4];
#pragma unroll
            for (int np = 0; np < 2; np++) {
                int k = ks + b_row;
                int n = colW0 + np * 16 + b_col;
                ldm_x4t(sptr(&ws_h[k * SWH + n]), bh[np][0], bh[np][1], bh[np][2], bh[np][3]);
                ldm_x4t(sptr(&ws_l[k * SWH + n]), bl[np][0], bl[np][1], bl[np][2], bl[np][3]);
            }
#pragma unroll
            for (int mt = 0; mt < 2; mt++) {
#pragma unroll
                for (int nt = 0; nt < 4; nt++) {
                    int np = nt >> 1, hf = (nt & 1) * 2;
                    mma16816(acc[mt][nt], ah[mt], bh[np][hf], bh[np][hf + 1]);
                    mma16816(acc[mt][nt], ah[mt], bl[np][hf], bl[np][hf + 1]);
                    mma16816(acc[mt][nt], al[mt], bh[np][hf], bh[np][hf + 1]);
                }
            }
        }
        __syncthreads();
    }

#pragma unroll
    for (int mt = 0; mt < 2; mt++) {
#pragma unroll
        for (int nt = 0; nt < 4; nt++) {
            int col = colW0 + nt * 8 + (lane & 3) * 2;
            int r0  = row0 + rowW0 + mt * 16 + (lane >> 2);
            int r1  = r0 + 8;
            if (r0 < N) {
                float s = g_dinv[r0];
                __half2 h = __floats2half2_rn(acc[mt][nt][0] * s, acc[mt][nt][1] * s);
                *(unsigned*)&g_hs[r0 * DOUT + col] = *(unsigned*)&h;
            }
            if (r1 < N) {
                float s = g_dinv[r1];
                __half2 h = __floats2half2_rn(acc[mt][nt][2] * s, acc[mt][nt][3] * s);
                *(unsigned*)&g_hs[r1 * DOUT + col] = *(unsigned*)&h;
            }
        }
    }
}

// ---------------------------------------------------------------------------
// FUSED agg1 + relu + gemm2:
//   Phase 1: x2[nl] = relu(dinv*(hs[nl] + sum_in hs[src]) + b1) -> smem fp16
//   Phase 2: g_hs2 = fp16((x2 @ W2) * dinv)   (X fp16 exact -> 2 mma/tile)
//   Block = 256 threads, 128 nodes/rows.
// ---------------------------------------------------------------------------
__global__ void __launch_bounds__(256)
k_agg1_gemm2(const float* __restrict__ b1, const float* __restrict__ W2, int N)
{
    constexpr int DOUT = 64;
    constexpr int SXH  = 136;          // x2 tile stride (halves), 128+8
    constexpr int SWH  = DOUT + 8;     // 72

    __shared__ __align__(16) __half xs[128 * SXH];     // 34816 B
    __shared__ __align__(16) __half ws_h[32 * SWH];    //  4608 B
    __shared__ __align__(16) __half ws_l[32 * SWH];    //  4608 B

    int t    = threadIdx.x;
    int row0 = blockIdx.x * 128;

    // ---- Phase 1: aggregate 128 nodes, 16 concurrently (16 thr/node x 8 col)
    {
        int sub = t >> 4;              // node-in-group 0..15
        int c8  = (t & 15) * 8;        // column base
        float bias[8];
#pragma unroll
        for (int q = 0; q < 8; q++) bias[q] = b1[c8 + q];

        for (int g = 0; g < 8; g++) {
            int nl   = g * 16 + sub;
            int node = row0 + nl;
            float a[8] = {0.f, 0.f, 0.f, 0.f, 0.f, 0.f, 0.f, 0.f};
            if (node < N) {
                uint4 v = *(const uint4*)&g_hs[node * 128 + c8];   // self loop
                float2 f0 = __half22float2(*(__half2*)&v.x);
                float2 f1 = __half22float2(*(__half2*)&v.y);
                float2 f2 = __half22float2(*(__half2*)&v.z);
                float2 f3 = __half22float2(*(__half2*)&v.w);
                a[0] = f0.x; a[1] = f0.y; a[2] = f1.x; a[3] = f1.y;
                a[4] = f2.x; a[5] = f2.y; a[6] = f3.x; a[7] = f3.y;

                int i = g_off[node];
                int e = g_off[node + 1];
                for (; i + 4 <= e; i += 4) {
                    int s0 = g_csr_src[i + 0];
                    int s1 = g_csr_src[i + 1];
                    int s2 = g_csr_src[i + 2];
                    int s3 = g_csr_src[i + 3];
                    uint4 v0 = *(const uint4*)&g_hs[s0 * 128 + c8];
                    uint4 v1 = *(const uint4*)&g_hs[s1 * 128 + c8];
                    uint4 v2 = *(const uint4*)&g_hs[s2 * 128 + c8];
                    uint4 v3 = *(const uint4*)&g_hs[s3 * 128 + c8];
#pragma unroll
                    for (int q = 0; q < 4; q++) {
                        unsigned w0 = (&v0.x)[q], w1 = (&v1.x)[q],
                                 w2 = (&v2.x)[q], w3 = (&v3.x)[q];
                        float2 f0q = __half22float2(*(__half2*)&w0);
                        float2 f1q = __half22float2(*(__half2*)&w1);
                        float2 f2q = __half22float2(*(__half2*)&w2);
                        float2 f3q = __half22float2(*(__half2*)&w3);
                        a[2 * q]     += f0q.x + f1q.x + f2q.x + f3q.x;
                        a[2 * q + 1] += f0q.y + f1q.y + f2q.y + f3q.y;
                    }
                }
                for (; i < e; i++) {
                    int s0 = g_csr_src[i];
                    uint4 vq = *(const uint4*)&g_hs[s0 * 128 + c8];
#pragma unroll
                    for (int q = 0; q < 4; q++) {
                        unsigned w0 = (&vq.x)[q];
                        float2 f = __half22float2(*(__half2*)&w0);
                        a[2 * q]     += f.x;
                        a[2 * q + 1] += f.y;
                    }
                }

                float d = g_dinv[node];
#pragma unroll
                for (int q = 0; q < 8; q++)
                    a[q] = fmaxf(a[q] * d + bias[q], 0.f);
            }
            __half2 h0 = __floats2half2_rn(a[0], a[1]);
            __half2 h1 = __floats2half2_rn(a[2], a[3]);
            __half2 h2 = __floats2half2_rn(a[4], a[5]);
            __half2 h3 = __floats2half2_rn(a[6], a[7]);
            uint4 o;
            o.x = *(unsigned*)&h0; o.y = *(unsigned*)&h1;
            o.z = *(unsigned*)&h2; o.w = *(unsigned*)&h3;
            *(uint4*)&xs[nl * SXH + c8] = o;
        }
    }
    __syncthreads();

    // ---- Phase 2: gemm2 from smem (X fp16 exact; W2 split h/l -> 2 mma)
    int w    = t >> 5;
    int lane = t & 31;
    int warpRow = w >> 1;              // WC=2, WR=4
    int warpCol = w & 1;
    int rowW0   = warpRow * 32;
    int colW0   = warpCol * 32;

    float acc[2][4][4];
#pragma unroll
    for (int mt = 0; mt < 2; mt++)
#pragma unroll
        for (int nt = 0; nt < 4; nt++)
#pragma unroll
            for (int q = 0; q < 4; q++) acc[mt][nt][q] = 0.f;

    int a_row = (lane & 15);
    int a_col = (lane >> 4) * 8;
    int b_row = ((lane >> 3) & 1) * 8 + (lane & 7);
    int b_col = (lane >> 4) * 8;

    for (int kk = 0; kk < 128; kk += 32) {
        // stage W2 chunk 32x64 split h/l (512 float4 slots, 2/thread)
#pragma unroll
        for (int u = 0; u < 2; u++) {
            int idx = u * 256 + t;
            int k   = idx >> 4;            // /16
            int c4  = idx & 15;
            float4 wv = *(const float4*)&W2[(kk + k) * DOUT + c4 * 4];
            uint2 hi, lo;
            split4(wv, hi, lo);
            *(uint2*)&ws_h[k * SWH + c4 * 4] = hi;
            *(uint2*)&ws_l[k * SWH + c4 * 4] = lo;
        }
        __syncthreads();

#pragma unroll
        for (int ks = 0; ks < 32; ks += 16) {
            unsigned af[2][4];
#pragma unroll
            for (int mt = 0; mt < 2; mt++) {
                int r = rowW0 + mt * 16 + a_row;
                int c = kk + ks + a_col;
                ldm_x4(sptr(&xs[r * SXH + c]), af[mt][0], af[mt][1], af[mt][2], af[mt][3]);
            }
            unsigned bh[2][4], bl[2][4];
#pragma unroll
            for (int np = 0; np < 2; np++) {
                int k = ks + b_row;
                int n = colW0 + np * 16 + b_col;
                ldm_x4t(sptr(&ws_h[k * SWH + n]), bh[np][0], bh[np][1], bh[np][2], bh[np][3]);
                ldm_x4t(sptr(&ws_l[k * SWH + n]), bl[np][0], bl[np][1], bl[np][2], bl[np][3]);
            }
#pragma unroll
            for (int mt = 0; mt < 2; mt++) {
#pragma unroll
                for (int nt = 0; nt < 4; nt++) {
                    int np = nt >> 1, hf = (nt & 1) * 2;
                    mma16816(acc[mt][nt], af[mt], bh[np][hf], bh[np][hf + 1]);
                    mma16816(acc[mt][nt], af[mt], bl[np][hf], bl[np][hf + 1]);
                }
            }
        }
        __syncthreads();
    }

    // epilogue: scale by dinv, store fp16 to g_hs2
#pragma unroll
    for (int mt = 0; mt < 2; mt++) {
#pragma unroll
        for (int nt = 0; nt < 4; nt++) {
            int col = colW0 + nt * 8 + (lane & 3) * 2;
            int r0  = row0 + rowW0 + mt * 16 + (lane >> 2);
            int r1  = r0 + 8;
            if (r0 < N) {
                float s = g_dinv[r0];
                __half2 h = __floats2half2_rn(acc[mt][nt][0] * s, acc[mt][nt][1] * s);
                *(unsigned*)&g_hs2[r0 * DOUT + col] = *(unsigned*)&h;
            }
            if (r1 < N) {
                float s = g_dinv[r1];
                __half2 h = __floats2half2_rn(acc[mt][nt][2] * s, acc[mt][nt][3] * s);
                *(unsigned*)&g_hs2[r1 * DOUT + col] = *(unsigned*)&h;
            }
        }
    }
}

// ---------------------------------------------------------------------------
// Final aggregate (layer 2): out[d] = dinv[d]*(hs2[d] + sum_in hs2[src]) + b2
// ---------------------------------------------------------------------------
__global__ void k_agg2(const float* __restrict__ bias,
                       float* __restrict__ outp, int N)
{
    constexpr int DOUT = 64;
    constexpr int TPN  = DOUT / 8;     // 8 threads per node
    constexpr int NPB  = 256 / TPN;    // 32 nodes per block

    int t    = threadIdx.x;
    int node = blockIdx.x * NPB + t / TPN;
    int c8   = (t % TPN) * 8;
    if (node >= N) return;

    float a[8];
    {
        uint4 v = *(const uint4*)&g_hs2[node * DOUT + c8];
        float2 f0 = __half22float2(*(__half2*)&v.x);
        float2 f1 = __half22float2(*(__half2*)&v.y);
        float2 f2 = __half22float2(*(__half2*)&v.z);
        float2 f3 = __half22float2(*(__half2*)&v.w);
        a[0] = f0.x; a[1] = f0.y; a[2] = f1.x; a[3] = f1.y;
        a[4] = f2.x; a[5] = f2.y; a[6] = f3.x; a[7] = f3.y;
    }

    int i = g_off[node];
    int e = g_off[node + 1];
    for (; i + 4 <= e; i += 4) {
        int s0 = g_csr_src[i + 0];
        int s1 = g_csr_src[i + 1];
        int s2 = g_csr_src[i + 2];
        int s3 = g_csr_src[i + 3];
        uint4 v0 = *(const uint4*)&g_hs2[s0 * DOUT + c8];
        uint4 v1 = *(const uint4*)&g_hs2[s1 * DOUT + c8];
        uint4 v2 = *(const uint4*)&g_hs2[s2 * DOUT + c8];
        uint4 v3 = *(const uint4*)&g_hs2[s3 * DOUT + c8];
#pragma unroll
        for (int q = 0; q < 4; q++) {
            unsigned w0 = (&v0.x)[q], w1 = (&v1.x)[q],
                     w2 = (&v2.x)[q], w3 = (&v3.x)[q];
            float2 f0 = __half22float2(*(__half2*)&w0);
            float2 f1 = __half22float2(*(__half2*)&w1);
            float2 f2 = __half22float2(*(__half2*)&w2);
            float2 f3 = __half22float2(*(__half2*)&w3);
            a[2 * q]     += f0.x + f1.x + f2.x + f3.x;
            a[2 * q + 1] += f0.y + f1.y + f2.y + f3.y;
        }
    }
    for (; i < e; i++) {
        int s0 = g_csr_src[i];
        uint4 v = *(const uint4*)&g_hs2[s0 * DOUT + c8];
#pragma unroll
        for (int q = 0; q < 4; q++) {
            unsigned w0 = (&v.x)[q];
            float2 f = __half22float2(*(__half2*)&w0);
            a[2 * q]     += f.x;
            a[2 * q + 1] += f.y;
        }
    }

    float d = g_dinv[node];
    float r[8];
#pragma unroll
    for (int q = 0; q < 8; q++)
        r[q] = a[q] * d + bias[c8 + q];
    float4 ob0 = make_float4(r[0], r[1], r[2], r[3]);
    float4 ob1 = make_float4(r[4], r[5], r[6], r[7]);
    *(float4*)&outp[node * DOUT + c8]     = ob0;
    *(float4*)&outp[node * DOUT + c8 + 4] = ob1;
}

// ---------------------------------------------------------------------------
extern "C" void kernel_launch(void* const* d_in, const int* in_sizes, int n_in,
                              void* d_out, int out_size)
{
    const float* e_prev = (const float*)d_in[0];
    const int*   ei     = (const int*)d_in[1];
    const float* W1     = (const float*)d_in[2];
    const float* b1     = (const float*)d_in[3];
    const float* W2     = (const float*)d_in[4];
    const float* b2     = (const float*)d_in[5];
    float*       out    = (float*)d_out;

    int N = in_sizes[0] / 128;   // 50000
    int E = in_sizes[1] / 2;     // 800000

    // CSR build (g_cnt arrives zeroed: statics at load, scan self-cleans)
    k_hist <<<(E / 8 + 255) / 256, 256>>>(ei, E, N);          // #1
    k_scan1<<<1, 1024>>>(N, E);                               // #2
    k_fill <<<(E / 8 + 255) / 256, 256>>>(ei, E, N);          // #3

    // Layer 1 GEMM
    k_gemm1<<<(N + 63) / 64, 256>>>(e_prev, W1, N);           // #4

    // Fused agg1 + relu + gemm2
    k_agg1_gemm2<<<(N + 127) / 128, 256>>>(b1, W2, N);        // #5

    // Final aggregate
    k_agg2<<<(N + 31) / 32, 256>>>(b2, out, N);               // #6
}

// round 12
// speedup vs baseline: 1.1284x; 1.1284x over previous
#include <cuda_runtime.h>
#include <cuda_fp16.h>

// ---------------------------------------------------------------------------
// GNNEncoder: 2-layer GCN. out[d] = dinv[d]*sum_{(s,d)}(x[s]@W)*dinv[s] + b
// R12: R10 un-fused pipeline (fusion regressed: serialized per-block agg)
//      + R11 CSR wins (no k_init, 8-edge hist/fill, self-cleaning scan)
//      + GEMM occupancy fix: __launch_bounds__(256,3) (was 2 CTAs/SM,
//        latency-bound at issue 25%).
// 7 launches: [hist, scan, fill, gemm1, agg1, gemm2, agg2]
// All scratch in __device__ globals; graph-capturable (kernel launches only).
// ---------------------------------------------------------------------------

#define NODES_MAX 50000
#define EDGES_MAX 800000

__device__ int    g_cnt[NODES_MAX];          // self-cleaning (zeroed by scan)
__device__ int    g_off[NODES_MAX + 1];
__device__ int    g_cursor[NODES_MAX];
__device__ int    g_csr_src[EDGES_MAX];
__device__ float  g_dinv[NODES_MAX];
__device__ __half g_hs [NODES_MAX * 128];    // layer1 (x@W1)*dinv  (gathered)
__device__ float  g_x2 [NODES_MAX * 128];    // layer1 output (post relu)
__device__ __half g_hs2[NODES_MAX * 64];     // layer2 (x2@W2)*dinv (gathered)

// ---- helpers ----------------------------------------------------------------
__device__ __forceinline__ unsigned sptr(const void* p)
{
    return (unsigned)__cvta_generic_to_shared(p);
}

__device__ __forceinline__ void ldm_x4(unsigned addr, unsigned& r0, unsigned& r1,
                                       unsigned& r2, unsigned& r3)
{
    asm volatile("ldmatrix.sync.aligned.m8n8.x4.shared.b16 {%0,%1,%2,%3}, [%4];"
                 : "=r"(r0), "=r"(r1), "=r"(r2), "=r"(r3) : "r"(addr));
}

__device__ __forceinline__ void ldm_x4t(unsigned addr, unsigned& r0, unsigned& r1,
                                        unsigned& r2, unsigned& r3)
{
    asm volatile("ldmatrix.sync.aligned.m8n8.x4.trans.shared.b16 {%0,%1,%2,%3}, [%4];"
                 : "=r"(r0), "=r"(r1), "=r"(r2), "=r"(r3) : "r"(addr));
}

__device__ __forceinline__ void mma16816(float* d, const unsigned* a,
                                         unsigned b0, unsigned b1)
{
    asm volatile(
        "mma.sync.aligned.m16n8k16.row.col.f32.f16.f16.f32 "
        "{%0,%1,%2,%3}, {%4,%5,%6,%7}, {%8,%9}, {%0,%1,%2,%3};"
        : "+f"(d[0]), "+f"(d[1]), "+f"(d[2]), "+f"(d[3])
        : "r"(a[0]), "r"(a[1]), "r"(a[2]), "r"(a[3]), "r"(b0), "r"(b1));
}

// split a float4 into hi/lo half2 pairs (x = h + l exactly to ~2^-22)
__device__ __forceinline__ void split4(float4 v, uint2& hi, uint2& lo)
{
    __half hx = __float2half_rn(v.x), hy = __float2half_rn(v.y);
    __half hz = __float2half_rn(v.z), hw = __float2half_rn(v.w);
    __half lx = __float2half_rn(v.x - __half2float(hx));
    __half ly = __float2half_rn(v.y - __half2float(hy));
    __half lz = __float2half_rn(v.z - __half2float(hz));
    __half lw = __float2half_rn(v.w - __half2float(hw));
    __half2 h01 = __halves2half2(hx, hy), h23 = __halves2half2(hz, hw);
    __half2 l01 = __halves2half2(lx, ly), l23 = __halves2half2(lz, lw);
    hi.x = *(unsigned*)&h01; hi.y = *(unsigned*)&h23;
    lo.x = *(unsigned*)&l01; lo.y = *(unsigned*)&l23;
}

// dtype detect: int64 viewed as int32 pairs -> odd words all zero.
__device__ __forceinline__ bool is_int32(const int* __restrict__ v)
{
    return (v[1] | v[3] | v[5] | v[7]) != 0;
}

// ---- CSR build --------------------------------------------------------------
__global__ void k_hist(const int* __restrict__ v, int E, int N)
{
    int base = (blockIdx.x * blockDim.x + threadIdx.x) * 8;
    if (base >= E) return;
    bool is32 = is_int32(v);
    if (base + 8 <= E) {
        unsigned d[8];
        if (is32) {
            int4 a = *(const int4*)&v[E + base];
            int4 b = *(const int4*)&v[E + base + 4];
            d[0] = a.x; d[1] = a.y; d[2] = a.z; d[3] = a.w;
            d[4] = b.x; d[5] = b.y; d[6] = b.z; d[7] = b.w;
        } else {
            int4 a = *(const int4*)&v[2 * E + 2 * base];
            int4 b = *(const int4*)&v[2 * E + 2 * base + 4];
            int4 c = *(const int4*)&v[2 * E + 2 * base + 8];
            int4 e = *(const int4*)&v[2 * E + 2 * base + 12];
            d[0] = a.x; d[1] = a.z; d[2] = b.x; d[3] = b.z;
            d[4] = c.x; d[5] = c.z; d[6] = e.x; d[7] = e.z;
        }
#pragma unroll
        for (int j = 0; j < 8; j++)
            if (d[j] < (unsigned)N) atomicAdd(&g_cnt[d[j]], 1);
    } else {
        int s = is32 ? 1 : 2, dbase = is32 ? E : 2 * E;
        for (int i = base; i < E; i++) {
            unsigned d = (unsigned)v[dbase + s * i];
            if (d < (unsigned)N) atomicAdd(&g_cnt[d], 1);
        }
    }
}

// Single-block coalesced block-scan; zeroes g_cnt after reading (self-clean).
__global__ void __launch_bounds__(1024) k_scan1(int N, int E)
{
    __shared__ int wsum[32];
    __shared__ int stot;
    int t    = threadIdx.x;
    int lane = t & 31;
    int wid  = t >> 5;
    int carry = 0;
    int ntiles = (N + 1023) >> 10;

    for (int tile = 0; tile < ntiles; tile++) {
        int i = (tile << 10) + t;
        int c = 0;
        if (i < N) {
            c = g_cnt[i];
            g_cnt[i] = 0;                    // self-clean for next launch
        }
        int incl = c;
#pragma unroll
        for (int o = 1; o < 32; o <<= 1) {
            int vv = __shfl_up_sync(0xffffffffu, incl, o);
            if (lane >= o) incl += vv;
        }
        if (lane == 31) wsum[wid] = incl;
        __syncthreads();
        if (wid == 0) {
            int s  = wsum[lane];
            int si = s;
#pragma unroll
            for (int o = 1; o < 32; o <<= 1) {
                int vv = __shfl_up_sync(0xffffffffu, si, o);
                if (lane >= o) si += vv;
            }
            wsum[lane] = si - s;
            if (lane == 31) stot = si;
        }
        __syncthreads();
        int off = carry + wsum[wid] + incl - c;
        if (i < N) {
            g_off[i]    = off;
            g_cursor[i] = off;
            g_dinv[i]   = rsqrtf((float)(c + 1));   // +1 self loop
        }
        carry += stot;
        __syncthreads();
    }
    if (t == 0) g_off[N] = E;
}

__global__ void k_fill(const int* __restrict__ v, int E, int N)
{
    int base = (blockIdx.x * blockDim.x + threadIdx.x) * 8;
    if (base >= E) return;
    bool is32 = is_int32(v);
    if (base + 8 <= E) {
        unsigned s[8], d[8];
        if (is32) {
            int4 a = *(const int4*)&v[base];
            int4 b = *(const int4*)&v[base + 4];
            int4 c = *(const int4*)&v[E + base];
            int4 e = *(const int4*)&v[E + base + 4];
            s[0] = a.x; s[1] = a.y; s[2] = a.z; s[3] = a.w;
            s[4] = b.x; s[5] = b.y; s[6] = b.z; s[7] = b.w;
            d[0] = c.x; d[1] = c.y; d[2] = c.z; d[3] = c.w;
            d[4] = e.x; d[5] = e.y; d[6] = e.z; d[7] = e.w;
        } else {
#pragma unroll
            for (int u = 0; u < 4; u++) {
                int4 a = *(const int4*)&v[2 * base + 4 * u];
                int4 c = *(const int4*)&v[2 * E + 2 * base + 4 * u];
                s[2 * u] = a.x; s[2 * u + 1] = a.z;
                d[2 * u] = c.x; d[2 * u + 1] = c.z;
            }
        }
#pragma unroll
        for (int j = 0; j < 8; j++)
            if (d[j] < (unsigned)N && s[j] < (unsigned)N)
                g_csr_src[atomicAdd(&g_cursor[d[j]], 1)] = (int)s[j];
    } else {
        int st = is32 ? 1 : 2, dbase = is32 ? E : 2 * E;
        for (int i = base; i < E; i++) {
            unsigned d  = (unsigned)v[dbase + st * i];
            unsigned sr = (unsigned)v[st * i];
            if (d < (unsigned)N && sr < (unsigned)N)
                g_csr_src[atomicAdd(&g_cursor[d], 1)] = (int)sr;
        }
    }
}

// ---------------------------------------------------------------------------
// Tensor-core GEMM with 2-term split (3 mma/tile):
//   H16[row] = fp16(((Xh+Xl)@(Wh+Wl))*dinv[row]); D = XhWh + XhWl + XlWh
// __launch_bounds__(256,3): regs capped ~85 -> 3 CTAs/SM (was 2, occ 23%).
// ---------------------------------------------------------------------------
template <int DOUT, int LAYER>
__global__ void __launch_bounds__(256, 3)
k_gemm(const float* __restrict__ Xp, const float* __restrict__ W, int N)
{
    constexpr int BK  = 32;
    constexpr int WC  = DOUT / 32;     // warp-cols (4 or 2)
    constexpr int WR  = 8 / WC;        // warp-rows (2 or 4)
    constexpr int BM  = WR * 32;       // block rows (64 or 128)
    constexpr int SXH = BK + 8;        // xs half-stride (40)
    constexpr int SWH = DOUT + 8;      // ws half-stride (136/72)

    const float* X = (LAYER == 0) ? Xp : g_x2;
    __half*      H = (LAYER == 0) ? g_hs : g_hs2;

    __shared__ __align__(16) __half xs_h[BM * SXH];
    __shared__ __align__(16) __half xs_l[BM * SXH];
    __shared__ __align__(16) __half ws_h[BK * SWH];
    __shared__ __align__(16) __half ws_l[BK * SWH];

    int t    = threadIdx.x;
    int w    = t >> 5;
    int lane = t & 31;
    int warpRow = w / WC;
    int warpCol = w % WC;
    int rowW0   = warpRow * 32;
    int colW0   = warpCol * 32;
    int row0    = blockIdx.x * BM;

    float acc[2][4][4];
#pragma unroll
    for (int mt = 0; mt < 2; mt++)
#pragma unroll
        for (int nt = 0; nt < 4; nt++)
#pragma unroll
            for (int q = 0; q < 4; q++) acc[mt][nt][q] = 0.f;

    int a_row = (lane & 15);
    int a_col = (lane >> 4) * 8;
    int b_row = ((lane >> 3) & 1) * 8 + (lane & 7);
    int b_col = (lane >> 4) * 8;

    for (int kk = 0; kk < 128; kk += BK) {
#pragma unroll
        for (int u = 0; u < BM / 32; u++) {
            int idx = u * 256 + t;
            int r   = idx >> 3;
            int j4  = idx & 7;
            int row = row0 + r;
            float4 x = make_float4(0.f, 0.f, 0.f, 0.f);
            if (row < N) x = *(const float4*)&X[row * 128 + kk + j4 * 4];
            uint2 hi, lo;
            split4(x, hi, lo);
            *(uint2*)&xs_h[r * SXH + j4 * 4] = hi;
            *(uint2*)&xs_l[r * SXH + j4 * 4] = lo;
        }
#pragma unroll
        for (int u = 0; u < DOUT / 32; u++) {
            int idx = u * 256 + t;
            int k   = idx / (DOUT / 4);
            int c4  = idx % (DOUT / 4);
            float4 wv = *(const float4*)&W[(kk + k) * DOUT + c4 * 4];
            uint2 hi, lo;
            split4(wv, hi, lo);
            *(uint2*)&ws_h[k * SWH + c4 * 4] = hi;
            *(uint2*)&ws_l[k * SWH + c4 * 4] = lo;
        }
        __syncthreads();

#pragma unroll
        for (int ks = 0; ks < BK; ks += 16) {
            unsigned ah[2][4], al[2][4];
#pragma unroll
            for (int mt = 0; mt < 2; mt++) {
                int r = rowW0 + mt * 16 + a_row;
                int c = ks + a_col;
                ldm_x4(sptr(&xs_h[r * SXH + c]), ah[mt][0], ah[mt][1], ah[mt][2], ah[mt][3]);
                ldm_x4(sptr(&xs_l[r * SXH + c]), al[mt][0], al[mt][1], al[mt][2], al[mt][3]);
            }
            unsigned bh[2][4], bl[2][4];
#pragma unroll
            for (int np = 0; np < 2; np++) {
                int k = ks + b_row;
                int n = colW0 + np * 16 + b_col;
                ldm_x4t(sptr(&ws_h[k * SWH + n]), bh[np][0], bh[np][1], bh[np][2], bh[np][3]);
                ldm_x4t(sptr(&ws_l[k * SWH + n]), bl[np][0], bl[np][1], bl[np][2], bl[np][3]);
            }
#pragma unroll
            for (int mt = 0; mt < 2; mt++) {
#pragma unroll
                for (int nt = 0; nt < 4; nt++) {
                    int np = nt >> 1, hf = (nt & 1) * 2;
                    mma16816(acc[mt][nt], ah[mt], bh[np][hf], bh[np][hf + 1]);
                    mma16816(acc[mt][nt], ah[mt], bl[np][hf], bl[np][hf + 1]);
                    mma16816(acc[mt][nt], al[mt], bh[np][hf], bh[np][hf + 1]);
                }
            }
        }
        __syncthreads();
    }

#pragma unroll
    for (int mt = 0; mt < 2; mt++) {
#pragma unroll
        for (int nt = 0; nt < 4; nt++) {
            int col = colW0 + nt * 8 + (lane & 3) * 2;
            int r0  = row0 + rowW0 + mt * 16 + (lane >> 2);
            int r1  = r0 + 8;
            if (r0 < N) {
                float s = g_dinv[r0];
                __half2 h = __floats2half2_rn(acc[mt][nt][0] * s, acc[mt][nt][1] * s);
                *(unsigned*)&H[r0 * DOUT + col] = *(unsigned*)&h;
            }
            if (r1 < N) {
                float s = g_dinv[r1];
                __half2 h = __floats2half2_rn(acc[mt][nt][2] * s, acc[mt][nt][3] * s);
                *(unsigned*)&H[r1 * DOUT + col] = *(unsigned*)&h;
            }
        }
    }
}

// ---------------------------------------------------------------------------
// Aggregate per dst node: OUT[d] = dinv[d]*(HS[d] + sum_in HS[src]) + b (+relu)
// ---------------------------------------------------------------------------
template <int DOUT, bool RELU, int LAYER>
__global__ void k_agg(const float* __restrict__ bias,
                      float* __restrict__ outp, int N)
{
    constexpr int TPN = DOUT / 8;
    constexpr int NPB = 256 / TPN;

    const __half* HS  = (LAYER == 0) ? g_hs : g_hs2;
    float*        OUT = (LAYER == 0) ? g_x2 : outp;

    int t    = threadIdx.x;
    int node = blockIdx.x * NPB + t / TPN;
    int c8   = (t % TPN) * 8;
    if (node >= N) return;

    float a[8];
    {
        uint4 v = *(const uint4*)&HS[node * DOUT + c8];
        float2 f0 = __half22float2(*(__half2*)&v.x);
        float2 f1 = __half22float2(*(__half2*)&v.y);
        float2 f2 = __half22float2(*(__half2*)&v.z);
        float2 f3 = __half22float2(*(__half2*)&v.w);
        a[0] = f0.x; a[1] = f0.y; a[2] = f1.x; a[3] = f1.y;
        a[4] = f2.x; a[5] = f2.y; a[6] = f3.x; a[7] = f3.y;
    }

    int i = g_off[node];
    int e = g_off[node + 1];
    for (; i + 4 <= e; i += 4) {
        int s0 = g_csr_src[i + 0];
        int s1 = g_csr_src[i + 1];
        int s2 = g_csr_src[i + 2];
        int s3 = g_csr_src[i + 3];
        uint4 v0 = *(const uint4*)&HS[s0 * DOUT + c8];
        uint4 v1 = *(const uint4*)&HS[s1 * DOUT + c8];
        uint4 v2 = *(const uint4*)&HS[s2 * DOUT + c8];
        uint4 v3 = *(const uint4*)&HS[s3 * DOUT + c8];
#pragma unroll
        for (int q = 0; q < 4; q++) {
            unsigned w0 = (&v0.x)[q], w1 = (&v1.x)[q],
                     w2 = (&v2.x)[q], w3 = (&v3.x)[q];
            float2 f0 = __half22float2(*(__half2*)&w0);
            float2 f1 = __half22float2(*(__half2*)&w1);
            float2 f2 = __half22float2(*(__half2*)&w2);
            float2 f3 = __half22float2(*(__half2*)&w3);
            a[2 * q]     += f0.x + f1.x + f2.x + f3.x;
            a[2 * q + 1] += f0.y + f1.y + f2.y + f3.y;
        }
    }
    for (; i < e; i++) {
        int s0 = g_csr_src[i];
        uint4 v = *(const uint4*)&HS[s0 * DOUT + c8];
#pragma unroll
        for (int q = 0; q < 4; q++) {
            unsigned w0 = (&v.x)[q];
            float2 f = __half22float2(*(__half2*)&w0);
            a[2 * q]     += f.x;
            a[2 * q + 1] += f.y;
        }
    }

    float d = g_dinv[node];
    float r[8];
#pragma unroll
    for (int q = 0; q < 8; q++) {
        float o = a[q] * d + bias[c8 + q];
        if (RELU) o = fmaxf(o, 0.f);
        r[q] = o;
    }
    float4 ob0 = make_float4(r[0], r[1], r[2], r[3]);
    float4 ob1 = make_float4(r[4], r[5], r[6], r[7]);
    *(float4*)&OUT[node * DOUT + c8]     = ob0;
    *(float4*)&OUT[node * DOUT + c8 + 4] = ob1;
}

// ---------------------------------------------------------------------------
extern "C" void kernel_launch(void* const* d_in, const int* in_sizes, int n_in,
                              void* d_out, int out_size)
{
    const float* e_prev = (const float*)d_in[0];
    const int*   ei     = (const int*)d_in[1];
    const float* W1     = (const float*)d_in[2];
    const float* b1     = (const float*)d_in[3];
    const float* W2     = (const float*)d_in[4];
    const float* b2     = (const float*)d_in[5];
    float*       out    = (float*)d_out;

    int N = in_sizes[0] / 128;   // 50000
    int E = in_sizes[1] / 2;     // 800000

    // CSR build (g_cnt arrives zeroed: statics at load, scan self-cleans)
    k_hist <<<(E / 8 + 255) / 256, 256>>>(ei, E, N);          // #1
    k_scan1<<<1, 1024>>>(N, E);                               // #2
    k_fill <<<(E / 8 + 255) / 256, 256>>>(ei, E, N);          // #3

    // Layer 1 (BM=64)
    k_gemm<128, 0><<<(N + 63) / 64, 256>>>(e_prev, W1, N);    // #4
    {
        constexpr int NPB = 256 / (128 / 8);
        k_agg<128, true, 0><<<(N + NPB - 1) / NPB, 256>>>(b1, nullptr, N); // #5
    }

    // Layer 2 (BM=128)
    k_gemm<64, 1><<<(N + 127) / 128, 256>>>(nullptr, W2, N);  // #6
    {
        constexpr int NPB = 256 / (64 / 8);
        k_agg<64, false, 1><<<(N + NPB - 1) / NPB, 256>>>(b2, out, N); // #7
    }
}

// round 13
// speedup vs baseline: 1.1417x; 1.0118x over previous
#include <cuda_runtime.h>
#include <cuda_fp16.h>

// ---------------------------------------------------------------------------
// GNNEncoder: 2-layer GCN. out[d] = dinv[d]*sum_{(s,d)}(x[s]@W)*dinv[s] + b
// R13: R12 with the 8-edge hist/fill regression reverted (4 edges/thread —
//      measured-best latency hiding for the atomic-bound CSR kernels).
//      Kept: no k_init (inline dtype detect), self-cleaning scan,
//      tensor-core split-mma GEMM with __launch_bounds__(256,3).
// 7 launches: [hist, scan, fill, gemm1, agg1, gemm2, agg2]
// All scratch in __device__ globals; graph-capturable (kernel launches only).
// ---------------------------------------------------------------------------

#define NODES_MAX 50000
#define EDGES_MAX 800000

__device__ int    g_cnt[NODES_MAX];          // self-cleaning (zeroed by scan)
__device__ int    g_off[NODES_MAX + 1];
__device__ int    g_cursor[NODES_MAX];
__device__ int    g_csr_src[EDGES_MAX];
__device__ float  g_dinv[NODES_MAX];
__device__ __half g_hs [NODES_MAX * 128];    // layer1 (x@W1)*dinv  (gathered)
__device__ float  g_x2 [NODES_MAX * 128];    // layer1 output (post relu)
__device__ __half g_hs2[NODES_MAX * 64];     // layer2 (x2@W2)*dinv (gathered)

// ---- helpers ----------------------------------------------------------------
__device__ __forceinline__ unsigned sptr(const void* p)
{
    return (unsigned)__cvta_generic_to_shared(p);
}

__device__ __forceinline__ void ldm_x4(unsigned addr, unsigned& r0, unsigned& r1,
                                       unsigned& r2, unsigned& r3)
{
    asm volatile("ldmatrix.sync.aligned.m8n8.x4.shared.b16 {%0,%1,%2,%3}, [%4];"
                 : "=r"(r0), "=r"(r1), "=r"(r2), "=r"(r3) : "r"(addr));
}

__device__ __forceinline__ void ldm_x4t(unsigned addr, unsigned& r0, unsigned& r1,
                                        unsigned& r2, unsigned& r3)
{
    asm volatile("ldmatrix.sync.aligned.m8n8.x4.trans.shared.b16 {%0,%1,%2,%3}, [%4];"
                 : "=r"(r0), "=r"(r1), "=r"(r2), "=r"(r3) : "r"(addr));
}

__device__ __forceinline__ void mma16816(float* d, const unsigned* a,
                                         unsigned b0, unsigned b1)
{
    asm volatile(
        "mma.sync.aligned.m16n8k16.row.col.f32.f16.f16.f32 "
        "{%0,%1,%2,%3}, {%4,%5,%6,%7}, {%8,%9}, {%0,%1,%2,%3};"
        : "+f"(d[0]), "+f"(d[1]), "+f"(d[2]), "+f"(d[3])
        : "r"(a[0]), "r"(a[1]), "r"(a[2]), "r"(a[3]), "r"(b0), "r"(b1));
}

// split a float4 into hi/lo half2 pairs (x = h + l exactly to ~2^-22)
__device__ __forceinline__ void split4(float4 v, uint2& hi, uint2& lo)
{
    __half hx = __float2half_rn(v.x), hy = __float2half_rn(v.y);
    __half hz = __float2half_rn(v.z), hw = __float2half_rn(v.w);
    __half lx = __float2half_rn(v.x - __half2float(hx));
    __half ly = __float2half_rn(v.y - __half2float(hy));
    __half lz = __float2half_rn(v.z - __half2float(hz));
    __half lw = __float2half_rn(v.w - __half2float(hw));
    __half2 h01 = __halves2half2(hx, hy), h23 = __halves2half2(hz, hw);
    __half2 l01 = __halves2half2(lx, ly), l23 = __halves2half2(lz, lw);
    hi.x = *(unsigned*)&h01; hi.y = *(unsigned*)&h23;
    lo.x = *(unsigned*)&l01; lo.y = *(unsigned*)&l23;
}

// dtype detect: int64 viewed as int32 pairs -> odd words all zero.
__device__ __forceinline__ bool is_int32(const int* __restrict__ v)
{
    return (v[1] | v[3] | v[5] | v[7]) != 0;
}

// ---- CSR build --------------------------------------------------------------
__global__ void k_hist(const int* __restrict__ v, int E, int N)
{
    int base = (blockIdx.x * blockDim.x + threadIdx.x) * 4;
    if (base >= E) return;
    bool is32 = is_int32(v);
    if (base + 4 <= E) {
        unsigned d0, d1, d2, d3;
        if (is32) {
            int4 a = *(const int4*)&v[E + base];
            d0 = a.x; d1 = a.y; d2 = a.z; d3 = a.w;
        } else {
            int4 a = *(const int4*)&v[2 * E + 2 * base];
            int4 b = *(const int4*)&v[2 * E + 2 * base + 4];
            d0 = a.x; d1 = a.z; d2 = b.x; d3 = b.z;
        }
        if (d0 < (unsigned)N) atomicAdd(&g_cnt[d0], 1);
        if (d1 < (unsigned)N) atomicAdd(&g_cnt[d1], 1);
        if (d2 < (unsigned)N) atomicAdd(&g_cnt[d2], 1);
        if (d3 < (unsigned)N) atomicAdd(&g_cnt[d3], 1);
    } else {
        int s = is32 ? 1 : 2, dbase = is32 ? E : 2 * E;
        for (int i = base; i < E; i++) {
            unsigned d = (unsigned)v[dbase + s * i];
            if (d < (unsigned)N) atomicAdd(&g_cnt[d], 1);
        }
    }
}

// Single-block coalesced block-scan; zeroes g_cnt after reading (self-clean).
__global__ void __launch_bounds__(1024) k_scan1(int N, int E)
{
    __shared__ int wsum[32];
    __shared__ int stot;
    int t    = threadIdx.x;
    int lane = t & 31;
    int wid  = t >> 5;
    int carry = 0;
    int ntiles = (N + 1023) >> 10;

    for (int tile = 0; tile < ntiles; tile++) {
        int i = (tile << 10) + t;
        int c = 0;
        if (i < N) {
            c = g_cnt[i];
            g_cnt[i] = 0;                    // self-clean for next launch
        }
        int incl = c;
#pragma unroll
        for (int o = 1; o < 32; o <<= 1) {
            int vv = __shfl_up_sync(0xffffffffu, incl, o);
            if (lane >= o) incl += vv;
        }
        if (lane == 31) wsum[wid] = incl;
        __syncthreads();
        if (wid == 0) {
            int s  = wsum[lane];
            int si = s;
#pragma unroll
            for (int o = 1; o < 32; o <<= 1) {
                int vv = __shfl_up_sync(0xffffffffu, si, o);
                if (lane >= o) si += vv;
            }
            wsum[lane] = si - s;
            if (lane == 31) stot = si;
        }
        __syncthreads();
        int off = carry + wsum[wid] + incl - c;
        if (i < N) {
            g_off[i]    = off;
            g_cursor[i] = off;
            g_dinv[i]   = rsqrtf((float)(c + 1));   // +1 self loop
        }
        carry += stot;
        __syncthreads();
    }
    if (t == 0) g_off[N] = E;
}

__global__ void k_fill(const int* __restrict__ v, int E, int N)
{
    int base = (blockIdx.x * blockDim.x + threadIdx.x) * 4;
    if (base >= E) return;
    bool is32 = is_int32(v);
    if (base + 4 <= E) {
        unsigned s0, s1, s2, s3, d0, d1, d2, d3;
        if (is32) {
            int4 a = *(const int4*)&v[base];
            int4 b = *(const int4*)&v[E + base];
            s0 = a.x; s1 = a.y; s2 = a.z; s3 = a.w;
            d0 = b.x; d1 = b.y; d2 = b.z; d3 = b.w;
        } else {
            int4 a = *(const int4*)&v[2 * base];
            int4 b = *(const int4*)&v[2 * base + 4];
            int4 c = *(const int4*)&v[2 * E + 2 * base];
            int4 d = *(const int4*)&v[2 * E + 2 * base + 4];
            s0 = a.x; s1 = a.z; s2 = b.x; s3 = b.z;
            d0 = c.x; d1 = c.z; d2 = d.x; d3 = d.z;
        }
        if (d0 < (unsigned)N && s0 < (unsigned)N)
            g_csr_src[atomicAdd(&g_cursor[d0], 1)] = (int)s0;
        if (d1 < (unsigned)N && s1 < (unsigned)N)
            g_csr_src[atomicAdd(&g_cursor[d1], 1)] = (int)s1;
        if (d2 < (unsigned)N && s2 < (unsigned)N)
            g_csr_src[atomicAdd(&g_cursor[d2], 1)] = (int)s2;
        if (d3 < (unsigned)N && s3 < (unsigned)N)
            g_csr_src[atomicAdd(&g_cursor[d3], 1)] = (int)s3;
    } else {
        int st = is32 ? 1 : 2, dbase = is32 ? E : 2 * E;
        for (int i = base; i < E; i++) {
            unsigned d  = (unsigned)v[dbase + st * i];
            unsigned sr = (unsigned)v[st * i];
            if (d < (unsigned)N && sr < (unsigned)N)
                g_csr_src[atomicAdd(&g_cursor[d], 1)] = (int)sr;
        }
    }
}

// ---------------------------------------------------------------------------
// Tensor-core GEMM with 2-term split (3 mma/tile):
//   H16[row] = fp16(((Xh+Xl)@(Wh+Wl))*dinv[row]); D = XhWh + XhWl + XlWh
// __launch_bounds__(256,3): 3 CTAs/SM.
// ---------------------------------------------------------------------------
template <int DOUT, int LAYER>
__global__ void __launch_bounds__(256, 3)
k_gemm(const float* __restrict__ Xp, const float* __restrict__ W, int N)
{
    constexpr int BK  = 32;
    constexpr int WC  = DOUT / 32;     // warp-cols (4 or 2)
    constexpr int WR  = 8 / WC;        // warp-rows (2 or 4)
    constexpr int BM  = WR * 32;       // block rows (64 or 128)
    constexpr int SXH = BK + 8;        // xs half-stride (40)
    constexpr int SWH = DOUT + 8;      // ws half-stride (136/72)

    const float* X = (LAYER == 0) ? Xp : g_x2;
    __half*      H = (LAYER == 0) ? g_hs : g_hs2;

    __shared__ __align__(16) __half xs_h[BM * SXH];
    __shared__ __align__(16) __half xs_l[BM * SXH];
    __shared__ __align__(16) __half ws_h[BK * SWH];
    __shared__ __align__(16) __half ws_l[BK * SWH];

    int t    = threadIdx.x;
    int w    = t >> 5;
    int lane = t & 31;
    int warpRow = w / WC;
    int warpCol = w % WC;
    int rowW0   = warpRow * 32;
    int colW0   = warpCol * 32;
    int row0    = blockIdx.x * BM;

    float acc[2][4][4];
#pragma unroll
    for (int mt = 0; mt < 2; mt++)
#pragma unroll
        for (int nt = 0; nt < 4; nt++)
#pragma unroll
            for (int q = 0; q < 4; q++) acc[mt][nt][q] = 0.f;

    int a_row = (lane & 15);
    int a_col = (lane >> 4) * 8;
    int b_row = ((lane >> 3) & 1) * 8 + (lane & 7);
    int b_col = (lane >> 4) * 8;

    for (int kk = 0; kk < 128; kk += BK) {
#pragma unroll
        for (int u = 0; u < BM / 32; u++) {
            int idx = u * 256 + t;
            int r   = idx >> 3;
            int j4  = idx & 7;
            int row = row0 + r;
            float4 x = make_float4(0.f, 0.f, 0.f, 0.f);
            if (row < N) x = *(const float4*)&X[row * 128 + kk + j4 * 4];
            uint2 hi, lo;
            split4(x, hi, lo);
            *(uint2*)&xs_h[r * SXH + j4 * 4] = hi;
            *(uint2*)&xs_l[r * SXH + j4 * 4] = lo;
        }
#pragma unroll
        for (int u = 0; u < DOUT / 32; u++) {
            int idx = u * 256 + t;
            int k   = idx / (DOUT / 4);
            int c4  = idx % (DOUT / 4);
            float4 wv = *(const float4*)&W[(kk + k) * DOUT + c4 * 4];
            uint2 hi, lo;
            split4(wv, hi, lo);
            *(uint2*)&ws_h[k * SWH + c4 * 4] = hi;
            *(uint2*)&ws_l[k * SWH + c4 * 4] = lo;
        }
        __syncthreads();

#pragma unroll
        for (int ks = 0; ks < BK; ks += 16) {
            unsigned ah[2][4], al[2][4];
#pragma unroll
            for (int mt = 0; mt < 2; mt++) {
                int r = rowW0 + mt * 16 + a_row;
                int c = ks + a_col;
                ldm_x4(sptr(&xs_h[r * SXH + c]), ah[mt][0], ah[mt][1], ah[mt][2], ah[mt][3]);
                ldm_x4(sptr(&xs_l[r * SXH + c]), al[mt][0], al[mt][1], al[mt][2], al[mt][3]);
            }
            unsigned bh[2][4], bl[2][4];
#pragma unroll
            for (int np = 0; np < 2; np++) {
                int k = ks + b_row;
                int n = colW0 + np * 16 + b_col;
                ldm_x4t(sptr(&ws_h[k * SWH + n]), bh[np][0], bh[np][1], bh[np][2], bh[np][3]);
                ldm_x4t(sptr(&ws_l[k * SWH + n]), bl[np][0], bl[np][1], bl[np][2], bl[np][3]);
            }
#pragma unroll
            for (int mt = 0; mt < 2; mt++) {
#pragma unroll
                for (int nt = 0; nt < 4; nt++) {
                    int np = nt >> 1, hf = (nt & 1) * 2;
                    mma16816(acc[mt][nt], ah[mt], bh[np][hf], bh[np][hf + 1]);
                    mma16816(acc[mt][nt], ah[mt], bl[np][hf], bl[np][hf + 1]);
                    mma16816(acc[mt][nt], al[mt], bh[np][hf], bh[np][hf + 1]);
                }
            }
        }
        __syncthreads();
    }

#pragma unroll
    for (int mt = 0; mt < 2; mt++) {
#pragma unroll
        for (int nt = 0; nt < 4; nt++) {
            int col = colW0 + nt * 8 + (lane & 3) * 2;
            int r0  = row0 + rowW0 + mt * 16 + (lane >> 2);
            int r1  = r0 + 8;
            if (r0 < N) {
                float s = g_dinv[r0];
                __half2 h = __floats2half2_rn(acc[mt][nt][0] * s, acc[mt][nt][1] * s);
                *(unsigned*)&H[r0 * DOUT + col] = *(unsigned*)&h;
            }
            if (r1 < N) {
                float s = g_dinv[r1];
                __half2 h = __floats2half2_rn(acc[mt][nt][2] * s, acc[mt][nt][3] * s);
                *(unsigned*)&H[r1 * DOUT + col] = *(unsigned*)&h;
            }
        }
    }
}

// ---------------------------------------------------------------------------
// Aggregate per dst node: OUT[d] = dinv[d]*(HS[d] + sum_in HS[src]) + b (+relu)
// ---------------------------------------------------------------------------
template <int DOUT, bool RELU, int LAYER>
__global__ void k_agg(const float* __restrict__ bias,
                      float* __restrict__ outp, int N)
{
    constexpr int TPN = DOUT / 8;
    constexpr int NPB = 256 / TPN;

    const __half* HS  = (LAYER == 0) ? g_hs : g_hs2;
    float*        OUT = (LAYER == 0) ? g_x2 : outp;

    int t    = threadIdx.x;
    int node = blockIdx.x * NPB + t / TPN;
    int c8   = (t % TPN) * 8;
    if (node >= N) return;

    float a[8];
    {
        uint4 v = *(const uint4*)&HS[node * DOUT + c8];
        float2 f0 = __half22float2(*(__half2*)&v.x);
        float2 f1 = __half22float2(*(__half2*)&v.y);
        float2 f2 = __half22float2(*(__half2*)&v.z);
        float2 f3 = __half22float2(*(__half2*)&v.w);
        a[0] = f0.x; a[1] = f0.y; a[2] = f1.x; a[3] = f1.y;
        a[4] = f2.x; a[5] = f2.y; a[6] = f3.x; a[7] = f3.y;
    }

    int i = __ldg(&g_off[node]);
    int e = __ldg(&g_off[node + 1]);
    for (; i + 4 <= e; i += 4) {
        int s0 = __ldg(&g_csr_src[i + 0]);
        int s1 = __ldg(&g_csr_src[i + 1]);
        int s2 = __ldg(&g_csr_src[i + 2]);
        int s3 = __ldg(&g_csr_src[i + 3]);
        uint4 v0 = *(const uint4*)&HS[s0 * DOUT + c8];
        uint4 v1 = *(const uint4*)&HS[s1 * DOUT + c8];
        uint4 v2 = *(const uint4*)&HS[s2 * DOUT + c8];
        uint4 v3 = *(const uint4*)&HS[s3 * DOUT + c8];
#pragma unroll
        for (int q = 0; q < 4; q++) {
            unsigned w0 = (&v0.x)[q], w1 = (&v1.x)[q],
                     w2 = (&v2.x)[q], w3 = (&v3.x)[q];
            float2 f0 = __half22float2(*(__half2*)&w0);
            float2 f1 = __half22float2(*(__half2*)&w1);
            float2 f2 = __half22float2(*(__half2*)&w2);
            float2 f3 = __half22float2(*(__half2*)&w3);
            a[2 * q]     += f0.x + f1.x + f2.x + f3.x;
            a[2 * q + 1] += f0.y + f1.y + f2.y + f3.y;
        }
    }
    for (; i < e; i++) {
        int s0 = __ldg(&g_csr_src[i]);
        uint4 v = *(const uint4*)&HS[s0 * DOUT + c8];
#pragma unroll
        for (int q = 0; q < 4; q++) {
            unsigned w0 = (&v.x)[q];
            float2 f = __half22float2(*(__half2*)&w0);
            a[2 * q]     += f.x;
            a[2 * q + 1] += f.y;
        }
    }

    float d = g_dinv[node];
    float r[8];
#pragma unroll
    for (int q = 0; q < 8; q++) {
        float o = a[q] * d + bias[c8 + q];
        if (RELU) o = fmaxf(o, 0.f);
        r[q] = o;
    }
    float4 ob0 = make_float4(r[0], r[1], r[2], r[3]);
    float4 ob1 = make_float4(r[4], r[5], r[6], r[7]);
    *(float4*)&OUT[node * DOUT + c8]     = ob0;
    *(float4*)&OUT[node * DOUT + c8 + 4] = ob1;
}

// ---------------------------------------------------------------------------
extern "C" void kernel_launch(void* const* d_in, const int* in_sizes, int n_in,
                              void* d_out, int out_size)
{
    const float* e_prev = (const float*)d_in[0];
    const int*   ei     = (const int*)d_in[1];
    const float* W1     = (const float*)d_in[2];
    const float* b1     = (const float*)d_in[3];
    const float* W2     = (const float*)d_in[4];
    const float* b2     = (const float*)d_in[5];
    float*       out    = (float*)d_out;

    int N = in_sizes[0] / 128;   // 50000
    int E = in_sizes[1] / 2;     // 800000

    // CSR build (g_cnt arrives zeroed: statics at load, scan self-cleans)
    k_hist <<<(E / 4 + 255) / 256, 256>>>(ei, E, N);          // #1
    k_scan1<<<1, 1024>>>(N, E);                               // #2
    k_fill <<<(E / 4 + 255) / 256, 256>>>(ei, E, N);          // #3

    // Layer 1 (BM=64)
    k_gemm<128, 0><<<(N + 63) / 64, 256>>>(e_prev, W1, N);    // #4
    {
        constexpr int NPB = 256 / (128 / 8);
        k_agg<128, true, 0><<<(N + NPB - 1) / NPB, 256>>>(b1, nullptr, N); // #5
    }

    // Layer 2 (BM=128)
    k_gemm<64, 1><<<(N + 127) / 128, 256>>>(nullptr, W2, N);  // #6
    {
        constexpr int NPB = 256 / (64 / 8);
        k_agg<64, false, 1><<<(N + NPB - 1) / NPB, 256>>>(b2, out, N); // #7
    }
}